// round 3
// baseline (speedup 1.0000x reference)
#include <cuda_runtime.h>
#include <math.h>

#define BATCH 16
#define SEQ   4096
#define D2    1024           // encoder feature dim = 2H
#define H     512
#define MDIM  (BATCH*SEQ)    // 65536

#define BM 128
#define BN 128
#define BK 16
#define TPB 256

// Scratch (no allocation allowed -> device globals)
__device__ float g_c[BATCH * H];        // per-batch precomputed hidden@W_h + bias
__device__ float g_scores[BATCH * SEQ]; // scores -> attention (in-place softmax)

// ---------------------------------------------------------------------------
// packed f32x2 helpers
// ---------------------------------------------------------------------------
__device__ __forceinline__ unsigned long long pack2(float x, float y) {
    unsigned long long r;
    asm("mov.b64 %0, {%1, %2};" : "=l"(r) : "f"(x), "f"(y));
    return r;
}
__device__ __forceinline__ void unpack2(unsigned long long v, float& lo, float& hi) {
    asm("mov.b64 {%0, %1}, %2;" : "=f"(lo), "=f"(hi) : "l"(v));
}
__device__ __forceinline__ void ffma2(unsigned long long& d,
                                      unsigned long long a,
                                      unsigned long long b) {
    asm("fma.rn.f32x2 %0, %1, %2, %0;" : "+l"(d) : "l"(a), "l"(b));
}

// ---------------------------------------------------------------------------
// K_init: zero scores scratch and output (d_out is poisoned 0xAA)
// ---------------------------------------------------------------------------
__global__ void k_init(float* __restrict__ out) {
    int i = blockIdx.x * blockDim.x + threadIdx.x;     // 65536 threads
    if (i < BATCH * SEQ) g_scores[i] = 0.0f;
    if (i < BATCH * D2)  out[i] = 0.0f;
}

// ---------------------------------------------------------------------------
// K0: c[b,h] = hidden[b,:] . W_attn[0:D2, h] + b_attn[h]
// grid = 16 blocks, 512 threads (one per h)
// ---------------------------------------------------------------------------
__global__ void k_precompute(const float* __restrict__ hidden,
                             const float* __restrict__ W,
                             const float* __restrict__ bias) {
    __shared__ float sh[D2];
    int b = blockIdx.x;
    for (int i = threadIdx.x; i < D2; i += blockDim.x) sh[i] = hidden[(size_t)b * D2 + i];
    __syncthreads();
    int h = threadIdx.x;
    float acc = bias[h];
#pragma unroll 8
    for (int k = 0; k < D2; ++k) acc = fmaf(sh[k], W[(size_t)k * H + h], acc);
    g_c[b * H + h] = acc;
}

// ---------------------------------------------------------------------------
// K1: fused GEMM (enc @ W_e) + tanh + dot(w_v) -> partial scores (atomic)
// 128x128x16 tile, 256 threads, 8x8 microtile computed as 8x4 f32x2 pairs.
// ---------------------------------------------------------------------------
__global__ __launch_bounds__(TPB)
void k_scores(const float* __restrict__ A,      // enc as [MDIM, D2] row-major
              const float* __restrict__ Wfull,  // W_attn [2*D2, H]
              const float* __restrict__ wv) {
    const float* Bmat = Wfull + (size_t)D2 * H;  // W_e [D2, H] row-major

    __shared__ float As[BK][BM + 4];   // padded: stride 132 floats
    __shared__ float Bs[BK][BN];
    __shared__ float s_score[BM];

    const int tid = threadIdx.x;
    const int m0 = blockIdx.x * BM;
    const int n0 = blockIdx.y * BN;
    const int bidx = m0 / SEQ;         // SEQ % BM == 0 -> tile within one batch

    if (tid < BM) s_score[tid] = 0.0f;

    // loader mapping
    const int a_row = tid >> 2;            // 0..63 (two passes of 64 rows)
    const int a_col = (tid & 3) * 4;       // 0,4,8,12
    const int b_row = tid >> 5;            // 0..7 (two passes of 8 rows)
    const int b_col = (tid & 31) * 4;      // 0..124

    const float* Aptr = A + (size_t)m0 * D2;

    float4 pa[2], pb[2];
#pragma unroll
    for (int r = 0; r < 2; r++)
        pa[r] = *(const float4*)(Aptr + (size_t)(a_row + r * 64) * D2 + a_col);
#pragma unroll
    for (int r = 0; r < 2; r++)
        pb[r] = *(const float4*)(Bmat + (size_t)(b_row + r * 8) * H + n0 + b_col);

    const int ty = tid >> 4;   // 0..15 -> rows ty*8..ty*8+7
    const int tx = tid & 15;   // 0..15 -> cols tx*8..tx*8+7

    unsigned long long acc[8][4];
#pragma unroll
    for (int i = 0; i < 8; i++)
#pragma unroll
        for (int j = 0; j < 4; j++) acc[i][j] = 0ull;

    const int NK = D2 / BK;  // 64
    for (int kt = 0; kt < NK; ++kt) {
        __syncthreads();
        // commit prefetched tile to smem (A transposed, padded)
#pragma unroll
        for (int r = 0; r < 2; r++) {
            int row = a_row + r * 64;
            As[a_col + 0][row] = pa[r].x;
            As[a_col + 1][row] = pa[r].y;
            As[a_col + 2][row] = pa[r].z;
            As[a_col + 3][row] = pa[r].w;
        }
#pragma unroll
        for (int r = 0; r < 2; r++)
            *(float4*)&Bs[b_row + r * 8][b_col] = pb[r];
        __syncthreads();

        // prefetch next k-tile into registers (overlap with compute)
        if (kt + 1 < NK) {
            int k0 = (kt + 1) * BK;
#pragma unroll
            for (int r = 0; r < 2; r++)
                pa[r] = *(const float4*)(Aptr + (size_t)(a_row + r * 64) * D2 + k0 + a_col);
#pragma unroll
            for (int r = 0; r < 2; r++)
                pb[r] = *(const float4*)(Bmat + (size_t)(k0 + b_row + r * 8) * H + n0 + b_col);
        }

#pragma unroll
        for (int k = 0; k < BK; k++) {
            float ra[8];
            *(float4*)&ra[0] = *(const float4*)&As[k][ty * 8];
            *(float4*)&ra[4] = *(const float4*)&As[k][ty * 8 + 4];
            unsigned long long rb[4];
            {
                ulonglong2 t0 = *(const ulonglong2*)&Bs[k][tx * 8];
                ulonglong2 t1 = *(const ulonglong2*)&Bs[k][tx * 8 + 4];
                rb[0] = t0.x; rb[1] = t0.y; rb[2] = t1.x; rb[3] = t1.y;
            }
#pragma unroll
            for (int i = 0; i < 8; i++) {
                unsigned long long aa = pack2(ra[i], ra[i]);
#pragma unroll
                for (int j = 0; j < 4; j++) ffma2(acc[i][j], aa, rb[j]);
            }
        }
    }

    // epilogue: + c[b,n], tanh, * w_v, reduce over n
    const float* cb = g_c + bidx * H + n0 + tx * 8;
    const float* wb = wv + n0 + tx * 8;
    float cv[8], wvv[8];
#pragma unroll
    for (int j = 0; j < 8; j++) { cv[j] = cb[j]; wvv[j] = wb[j]; }

#pragma unroll
    for (int i = 0; i < 8; i++) {
        float sum = 0.0f;
#pragma unroll
        for (int j = 0; j < 4; j++) {
            float lo, hi;
            unpack2(acc[i][j], lo, hi);
            sum += tanhf(lo + cv[2 * j])     * wvv[2 * j];
            sum += tanhf(hi + cv[2 * j + 1]) * wvv[2 * j + 1];
        }
        atomicAdd(&s_score[ty * 8 + i], sum);
    }
    __syncthreads();
    if (tid < BM) atomicAdd(&g_scores[m0 + tid], s_score[tid]);
}

// ---------------------------------------------------------------------------
// K2: softmax over S per batch, in place on g_scores. 16 blocks x 256 threads.
// ---------------------------------------------------------------------------
__global__ void k_softmax() {
    int b = blockIdx.x, tid = threadIdx.x;
    float* sc = g_scores + (size_t)b * SEQ;
    __shared__ float sh[8];
    __shared__ float bc;

    float mx = -3.4e38f;
    for (int i = tid; i < SEQ; i += 256) mx = fmaxf(mx, sc[i]);
#pragma unroll
    for (int o = 16; o > 0; o >>= 1) mx = fmaxf(mx, __shfl_xor_sync(0xffffffffu, mx, o));
    if ((tid & 31) == 0) sh[tid >> 5] = mx;
    __syncthreads();
    if (tid == 0) {
        float m = sh[0];
        for (int i = 1; i < 8; i++) m = fmaxf(m, sh[i]);
        bc = m;
    }
    __syncthreads();
    mx = bc;

    float sum = 0.0f;
    for (int i = tid; i < SEQ; i += 256) {
        float e = expf(sc[i] - mx);
        sc[i] = e;
        sum += e;
    }
#pragma unroll
    for (int o = 16; o > 0; o >>= 1) sum += __shfl_xor_sync(0xffffffffu, sum, o);
    if ((tid & 31) == 0) sh[tid >> 5] = sum;
    __syncthreads();
    if (tid == 0) {
        float s = 0.0f;
        for (int i = 0; i < 8; i++) s += sh[i];
        bc = 1.0f / s;
    }
    __syncthreads();
    float inv = bc;
    for (int i = tid; i < SEQ; i += 256) sc[i] *= inv;
}

// ---------------------------------------------------------------------------
// K3: context[b,d] = sum_s attn[b,s] * enc[b,s,d]  (streaming, float4)
// grid (SEQ/256, BATCH), 256 threads; each thread owns one float4 column group.
// ---------------------------------------------------------------------------
__global__ void k_context(const float* __restrict__ enc, float* __restrict__ out) {
    int b = blockIdx.y;
    int s0 = blockIdx.x * 256;
    int col = threadIdx.x * 4;

    const float* attn = g_scores + (size_t)b * SEQ + s0;
    const float* base = enc + ((size_t)b * SEQ + s0) * D2 + col;

    float4 acc = make_float4(0.f, 0.f, 0.f, 0.f);
#pragma unroll 4
    for (int s = 0; s < 256; s++) {
        float a = attn[s];
        float4 e = *(const float4*)(base + (size_t)s * D2);
        acc.x = fmaf(a, e.x, acc.x);
        acc.y = fmaf(a, e.y, acc.y);
        acc.z = fmaf(a, e.z, acc.z);
        acc.w = fmaf(a, e.w, acc.w);
    }
    float* o = out + (size_t)b * D2 + col;
    atomicAdd(&o[0], acc.x);
    atomicAdd(&o[1], acc.y);
    atomicAdd(&o[2], acc.z);
    atomicAdd(&o[3], acc.w);
}

// ---------------------------------------------------------------------------
extern "C" void kernel_launch(void* const* d_in, const int* in_sizes, int n_in,
                              void* d_out, int out_size) {
    const float* hidden = (const float*)d_in[0];  // [16, 1024]
    const float* enc    = (const float*)d_in[1];  // [16, 4096, 1024]
    const float* W      = (const float*)d_in[2];  // [2048, 512]
    const float* bias   = (const float*)d_in[3];  // [512]
    const float* wv     = (const float*)d_in[4];  // [512]
    float* out = (float*)d_out;                   // [16, 1024]

    k_init<<<256, 256>>>(out);
    k_precompute<<<BATCH, H>>>(hidden, W, bias);

    dim3 g1(MDIM / BM, H / BN);   // (512, 4)
    k_scores<<<g1, TPB>>>(enc, W, wv);

    k_softmax<<<BATCH, 256>>>();

    dim3 g3(SEQ / 256, BATCH);    // (16, 16)
    k_context<<<g3, 256>>>(enc, out);
}

// round 7
// speedup vs baseline: 2.2712x; 2.2712x over previous
#include <cuda_runtime.h>
#include <cuda_bf16.h>
#include <cstdint>
#include <math.h>

#define BATCH 16
#define SEQ   4096
#define D2    1024
#define H     512
#define MDIM  (BATCH*SEQ)      // 65536

// ---- GEMM tiling ----
#define KT      64             // k-tile (64 bf16 = 128B rows, SW128-style swizzle)
#define NKT     (D2/KT)        // 16
#define TILE_M  128
#define TILE_N  128

// per-stage smem layout (bytes)
#define AH_OFF 0
#define AL_OFF 16384
#define BH_OFF 32768
#define BL_OFF 49152
#define STAGE_BYTES 65536
#define SMEM_ALLOC (2*STAGE_BYTES + 256)

// ---------------------------------------------------------------------------
// Device-global scratch (no allocation allowed)
// ---------------------------------------------------------------------------
__device__ __align__(16) __nv_bfloat16 g_Ah[(size_t)MDIM * D2];   // 128MB
__device__ __align__(16) __nv_bfloat16 g_Al[(size_t)MDIM * D2];   // 128MB
__device__ __align__(16) __nv_bfloat16 g_Bh[(size_t)H * D2];      // 1MB  (W_e^T, [n][k])
__device__ __align__(16) __nv_bfloat16 g_Bl[(size_t)H * D2];      // 1MB
__device__ float g_c[BATCH * H];
__device__ float g_scores[BATCH * SEQ];

// ---------------------------------------------------------------------------
// PTX helpers (baseline ISA only: works on plain sm_103 target)
// ---------------------------------------------------------------------------
__device__ __forceinline__ uint32_t smem_u32(const void* p) {
    uint32_t a;
    asm("{ .reg .u64 t; cvta.to.shared.u64 t, %1; cvt.u32.u64 %0, t; }" : "=r"(a) : "l"(p));
    return a;
}
__device__ __forceinline__ void cpa16(uint32_t s, const void* g) {
    asm volatile("cp.async.cg.shared.global [%0], [%1], 16;" :: "r"(s), "l"(g) : "memory");
}
__device__ __forceinline__ void ldsm4(uint32_t* r, uint32_t addr) {
    asm volatile("ldmatrix.sync.aligned.m8n8.x4.shared.b16 {%0,%1,%2,%3}, [%4];"
        : "=r"(r[0]), "=r"(r[1]), "=r"(r[2]), "=r"(r[3]) : "r"(addr));
}
__device__ __forceinline__ void mma16816(float* d, const uint32_t* a,
                                         uint32_t b0, uint32_t b1) {
    asm volatile(
        "mma.sync.aligned.m16n8k16.row.col.f32.bf16.bf16.f32 "
        "{%0,%1,%2,%3}, {%4,%5,%6,%7}, {%8,%9}, {%0,%1,%2,%3};"
        : "+f"(d[0]), "+f"(d[1]), "+f"(d[2]), "+f"(d[3])
        : "r"(a[0]), "r"(a[1]), "r"(a[2]), "r"(a[3]), "r"(b0), "r"(b1));
}
__device__ __forceinline__ uint32_t swz(uint32_t o) { return o ^ ((o >> 3) & 0x70); }

// ---------------------------------------------------------------------------
// K_init
// ---------------------------------------------------------------------------
__global__ void k_init(float* __restrict__ out) {
    int i = blockIdx.x * blockDim.x + threadIdx.x;
    if (i < BATCH * SEQ) g_scores[i] = 0.0f;
    if (i < BATCH * D2)  out[i] = 0.0f;
}

// ---------------------------------------------------------------------------
// K_precompute: c[b,h] = hidden[b,:] . W_attn[0:D2, h] + b_attn[h]
// ---------------------------------------------------------------------------
__global__ void k_precompute(const float* __restrict__ hidden,
                             const float* __restrict__ W,
                             const float* __restrict__ bias) {
    __shared__ float sh[D2];
    int b = blockIdx.x;
    for (int i = threadIdx.x; i < D2; i += blockDim.x) sh[i] = hidden[(size_t)b * D2 + i];
    __syncthreads();
    int h = threadIdx.x;
    float acc = bias[h];
#pragma unroll 8
    for (int k = 0; k < D2; ++k) acc = fmaf(sh[k], W[(size_t)k * H + h], acc);
    g_c[b * H + h] = acc;
}

// ---------------------------------------------------------------------------
// K_convB: W_e[k][n] -> g_Bh/g_Bl[n][k]  (bf16 hi/lo, transposed to n-major)
// ---------------------------------------------------------------------------
__global__ void k_convB(const float* __restrict__ W) {
    int idx = blockIdx.x * blockDim.x + threadIdx.x;   // H*D2
    int n = idx >> 10, k = idx & 1023;
    float x = W[(size_t)(D2 + k) * H + n];
    __nv_bfloat16 hi = __float2bfloat16(x);
    g_Bh[idx] = hi;
    g_Bl[idx] = __float2bfloat16(x - __bfloat162float(hi));
}

// ---------------------------------------------------------------------------
// K_convA: enc fp32 -> g_Ah/g_Al bf16 hi/lo (row-major unchanged)
// ---------------------------------------------------------------------------
__global__ void k_convA(const float4* __restrict__ enc4) {
    size_t i = (size_t)blockIdx.x * blockDim.x + threadIdx.x;   // MDIM*D2/4
    float4 v = enc4[i];
    __nv_bfloat16 h0 = __float2bfloat16(v.x), h1 = __float2bfloat16(v.y);
    __nv_bfloat16 h2 = __float2bfloat16(v.z), h3 = __float2bfloat16(v.w);
    __nv_bfloat162* ah = (__nv_bfloat162*)g_Ah;
    __nv_bfloat162* al = (__nv_bfloat162*)g_Al;
    ah[2*i]   = __halves2bfloat162(h0, h1);
    ah[2*i+1] = __halves2bfloat162(h2, h3);
    al[2*i]   = __halves2bfloat162(__float2bfloat16(v.x - __bfloat162float(h0)),
                                   __float2bfloat16(v.y - __bfloat162float(h1)));
    al[2*i+1] = __halves2bfloat162(__float2bfloat16(v.z - __bfloat162float(h2)),
                                   __float2bfloat16(v.w - __bfloat162float(h3)));
}

// ---------------------------------------------------------------------------
// K_scores: mma.sync bf16 3-term GEMM + tanh + dot(w_v) epilogue.
// Grid (4, 512): x = N tile (128 cols), y = M tile (128 rows). 256 threads.
// ---------------------------------------------------------------------------
__device__ __forceinline__ void load_tile(uint32_t stage, int kt, int m0, int n0, int tid) {
    const size_t kOff = (size_t)kt * KT;
#pragma unroll
    for (int i = 0; i < 4; ++i) {          // A: 128 rows x 8 16B-chunks = 1024
        int c = tid + 256 * i;
        int row = c >> 3, c16 = c & 7;
        uint32_t so = swz((uint32_t)(row * 128 + c16 * 16));
        size_t e = (size_t)(m0 + row) * D2 + kOff + c16 * 8;
        cpa16(stage + AH_OFF + so, g_Ah + e);
        cpa16(stage + AL_OFF + so, g_Al + e);
    }
#pragma unroll
    for (int i = 0; i < 4; ++i) {          // B: 128 rows x 8 chunks = 1024
        int c = tid + 256 * i;
        int row = c >> 3, c16 = c & 7;
        uint32_t so = swz((uint32_t)(row * 128 + c16 * 16));
        size_t e = (size_t)(n0 + row) * D2 + kOff + c16 * 8;
        cpa16(stage + BH_OFF + so, g_Bh + e);
        cpa16(stage + BL_OFF + so, g_Bl + e);
    }
}

__global__ void __launch_bounds__(256, 1)
k_scores(const float* __restrict__ wv) {
    extern __shared__ char smem[];
    uint32_t sb = smem_u32(smem);
    sb = (sb + 127u) & ~127u;

    const int tid = threadIdx.x;
    const int wid = tid >> 5, lane = tid & 31;
    const int warp_m = wid >> 2;          // 0..1  -> M offset *64
    const int warp_n = wid & 3;           // 0..3  -> N offset *32
    const int g = lane >> 2, t = lane & 3;

    const int n0 = blockIdx.x * TILE_N;
    const int m0 = blockIdx.y * TILE_M;

    __shared__ float s_score[TILE_M];
    if (tid < TILE_M) s_score[tid] = 0.0f;

    // ldmatrix lane addressing constants
    const int a_lm = ((lane >> 3) & 1) * 8 + (lane & 7);   // m within 16
    const int a_kb = (lane >> 4) * 16;                     // k-byte within 32
    const int b_ln = (lane >> 4) * 8 + (lane & 7);         // n within 16
    const int b_kb = ((lane >> 3) & 1) * 16;

    float d[4][4][4];                     // [mt][nt][frag]
#pragma unroll
    for (int mt = 0; mt < 4; mt++)
#pragma unroll
        for (int nt = 0; nt < 4; nt++)
#pragma unroll
            for (int e = 0; e < 4; e++) d[mt][nt][e] = 0.0f;

    // prologue: tile 0 -> stage 0
    load_tile(sb, 0, m0, n0, tid);
    asm volatile("cp.async.commit_group;" ::: "memory");

    for (int kt = 0; kt < NKT; ++kt) {
        const uint32_t cur = sb + (uint32_t)(kt & 1) * STAGE_BYTES;
        __syncthreads();   // everyone done computing the stage we are about to overwrite
        if (kt + 1 < NKT) {
            load_tile(sb + (uint32_t)((kt + 1) & 1) * STAGE_BYTES, kt + 1, m0, n0, tid);
            asm volatile("cp.async.commit_group;" ::: "memory");
            asm volatile("cp.async.wait_group 1;" ::: "memory");
        } else {
            asm volatile("cp.async.wait_group 0;" ::: "memory");
        }
        __syncthreads();

#pragma unroll
        for (int ks = 0; ks < 4; ++ks) {
            uint32_t ah[4][4], al[4][4], bh[2][4], bl[2][4];
#pragma unroll
            for (int mt = 0; mt < 4; mt++) {
                uint32_t off = swz((uint32_t)((warp_m * 64 + mt * 16 + a_lm) * 128
                                              + ks * 32 + a_kb));
                ldsm4(ah[mt], cur + AH_OFF + off);
                ldsm4(al[mt], cur + AL_OFF + off);
            }
#pragma unroll
            for (int p = 0; p < 2; p++) {
                uint32_t off = swz((uint32_t)((warp_n * 32 + p * 16 + b_ln) * 128
                                              + ks * 32 + b_kb));
                ldsm4(bh[p], cur + BH_OFF + off);
                ldsm4(bl[p], cur + BL_OFF + off);
            }
            // three passes keep same-accumulator MMAs 16 instructions apart
#pragma unroll
            for (int mt = 0; mt < 4; mt++)
#pragma unroll
                for (int nt = 0; nt < 4; nt++)
                    mma16816(d[mt][nt], ah[mt], bh[nt >> 1][(nt & 1) * 2], bh[nt >> 1][(nt & 1) * 2 + 1]);
#pragma unroll
            for (int mt = 0; mt < 4; mt++)
#pragma unroll
                for (int nt = 0; nt < 4; nt++)
                    mma16816(d[mt][nt], ah[mt], bl[nt >> 1][(nt & 1) * 2], bl[nt >> 1][(nt & 1) * 2 + 1]);
#pragma unroll
            for (int mt = 0; mt < 4; mt++)
#pragma unroll
                for (int nt = 0; nt < 4; nt++)
                    mma16816(d[mt][nt], al[mt], bh[nt >> 1][(nt & 1) * 2], bh[nt >> 1][(nt & 1) * 2 + 1]);
        }
    }

    // epilogue: tanh + dot(w_v), reduce to per-row scores
    const int b = m0 >> 12;
    float cv[8], wvv[8];
#pragma unroll
    for (int nt = 0; nt < 4; nt++)
#pragma unroll
        for (int e = 0; e < 2; e++) {
            int n = n0 + warp_n * 32 + nt * 8 + t * 2 + e;
            cv[nt * 2 + e]  = g_c[b * H + n];
            wvv[nt * 2 + e] = wv[n];
        }

#pragma unroll
    for (int mt = 0; mt < 4; mt++) {
        float r0 = 0.0f, r1 = 0.0f;      // rows g and g+8 of this m-tile
#pragma unroll
        for (int nt = 0; nt < 4; nt++) {
            r0 = fmaf(tanhf(d[mt][nt][0] + cv[nt * 2]),     wvv[nt * 2],     r0);
            r0 = fmaf(tanhf(d[mt][nt][1] + cv[nt * 2 + 1]), wvv[nt * 2 + 1], r0);
            r1 = fmaf(tanhf(d[mt][nt][2] + cv[nt * 2]),     wvv[nt * 2],     r1);
            r1 = fmaf(tanhf(d[mt][nt][3] + cv[nt * 2 + 1]), wvv[nt * 2 + 1], r1);
        }
        r0 += __shfl_xor_sync(0xffffffffu, r0, 1);
        r0 += __shfl_xor_sync(0xffffffffu, r0, 2);
        r1 += __shfl_xor_sync(0xffffffffu, r1, 1);
        r1 += __shfl_xor_sync(0xffffffffu, r1, 2);
        if (t == 0) {
            atomicAdd(&s_score[warp_m * 64 + mt * 16 + g],     r0);
            atomicAdd(&s_score[warp_m * 64 + mt * 16 + 8 + g], r1);
        }
    }
    __syncthreads();
    if (tid < TILE_M) atomicAdd(&g_scores[m0 + tid], s_score[tid]);
}

// ---------------------------------------------------------------------------
// K_softmax: per-batch softmax over S, in place.
// ---------------------------------------------------------------------------
__global__ void k_softmax() {
    int b = blockIdx.x, tid = threadIdx.x;
    float* sc = g_scores + (size_t)b * SEQ;
    __shared__ float sh[8];
    __shared__ float bc;

    float mx = -3.4e38f;
    for (int i = tid; i < SEQ; i += 256) mx = fmaxf(mx, sc[i]);
#pragma unroll
    for (int o = 16; o > 0; o >>= 1) mx = fmaxf(mx, __shfl_xor_sync(0xffffffffu, mx, o));
    if ((tid & 31) == 0) sh[tid >> 5] = mx;
    __syncthreads();
    if (tid == 0) {
        float m = sh[0];
        for (int i = 1; i < 8; i++) m = fmaxf(m, sh[i]);
        bc = m;
    }
    __syncthreads();
    mx = bc;

    float sum = 0.0f;
    for (int i = tid; i < SEQ; i += 256) {
        float e = expf(sc[i] - mx);
        sc[i] = e;
        sum += e;
    }
#pragma unroll
    for (int o = 16; o > 0; o >>= 1) sum += __shfl_xor_sync(0xffffffffu, sum, o);
    if ((tid & 31) == 0) sh[tid >> 5] = sum;
    __syncthreads();
    if (tid == 0) {
        float s = 0.0f;
        for (int i = 0; i < 8; i++) s += sh[i];
        bc = 1.0f / s;
    }
    __syncthreads();
    float inv = bc;
    for (int i = tid; i < SEQ; i += 256) sc[i] *= inv;
}

// ---------------------------------------------------------------------------
// K_context: context[b,d] = sum_s attn[b,s] * enc[b,s,d]
// ---------------------------------------------------------------------------
__global__ void k_context(const float* __restrict__ enc, float* __restrict__ out) {
    int b = blockIdx.y;
    int s0 = blockIdx.x * 256;
    int col = threadIdx.x * 4;

    const float* attn = g_scores + (size_t)b * SEQ + s0;
    const float* base = enc + ((size_t)b * SEQ + s0) * D2 + col;

    float4 acc = make_float4(0.f, 0.f, 0.f, 0.f);
#pragma unroll 4
    for (int s = 0; s < 256; s++) {
        float a = attn[s];
        float4 e = *(const float4*)(base + (size_t)s * D2);
        acc.x = fmaf(a, e.x, acc.x);
        acc.y = fmaf(a, e.y, acc.y);
        acc.z = fmaf(a, e.z, acc.z);
        acc.w = fmaf(a, e.w, acc.w);
    }
    float* o = out + (size_t)b * D2 + col;
    atomicAdd(&o[0], acc.x);
    atomicAdd(&o[1], acc.y);
    atomicAdd(&o[2], acc.z);
    atomicAdd(&o[3], acc.w);
}

// ---------------------------------------------------------------------------
extern "C" void kernel_launch(void* const* d_in, const int* in_sizes, int n_in,
                              void* d_out, int out_size) {
    const float* hidden = (const float*)d_in[0];  // [16, 1024]
    const float* enc    = (const float*)d_in[1];  // [16, 4096, 1024]
    const float* W      = (const float*)d_in[2];  // [2048, 512]
    const float* bias   = (const float*)d_in[3];  // [512]
    const float* wv     = (const float*)d_in[4];  // [512]
    float* out = (float*)d_out;                   // [16, 1024]

    static bool attr_set = false;
    if (!attr_set) {
        cudaFuncSetAttribute(k_scores, cudaFuncAttributeMaxDynamicSharedMemorySize, SMEM_ALLOC);
        attr_set = true;
    }

    k_init<<<256, 256>>>(out);
    k_precompute<<<BATCH, H>>>(hidden, W, bias);
    k_convB<<<(H * D2) / 256, 256>>>(W);
    k_convA<<<(int)(((size_t)MDIM * D2 / 4) / 256), 256>>>((const float4*)enc);

    dim3 gs(H / TILE_N, MDIM / TILE_M);   // (4, 512)
    k_scores<<<gs, 256, SMEM_ALLOC>>>(wv);

    k_softmax<<<BATCH, 256>>>();

    dim3 gc(SEQ / 256, BATCH);
    k_context<<<gc, 256>>>(enc, out);
}

// round 8
// speedup vs baseline: 2.3072x; 1.0158x over previous
#include <cuda_runtime.h>
#include <cuda_bf16.h>
#include <cstdint>
#include <math.h>

#define BATCH 16
#define SEQ   4096
#define D2    1024
#define H     512
#define MDIM  (BATCH*SEQ)      // 65536

// ---- GEMM tiling ----
#define KT      64             // k-tile (64 bf16 = 128B rows)
#define NKT     (D2/KT)        // 16
#define TILE_M  128
#define TILE_N  256

// per-stage smem layout (bytes)
#define AH_OFF 0
#define AL_OFF 16384
#define BH_OFF 32768
#define BL_OFF 65536
#define STAGE_BYTES 98304      // 96 KB
#define SMEM_ALLOC (2*STAGE_BYTES + 256)

// ---------------------------------------------------------------------------
// Device-global scratch (no allocation allowed)
// ---------------------------------------------------------------------------
__device__ __align__(16) __nv_bfloat16 g_Ah[(size_t)MDIM * D2];   // 128MB
__device__ __align__(16) __nv_bfloat16 g_Al[(size_t)MDIM * D2];   // 128MB
__device__ __align__(16) __nv_bfloat16 g_Bh[(size_t)H * D2];      // 1MB  (W_e^T, [n][k])
__device__ __align__(16) __nv_bfloat16 g_Bl[(size_t)H * D2];      // 1MB
__device__ float g_c[BATCH * H];
__device__ float g_scores[BATCH * SEQ];

// ---------------------------------------------------------------------------
// PTX helpers (baseline ISA only: works on plain sm_103 target)
// ---------------------------------------------------------------------------
__device__ __forceinline__ uint32_t smem_u32(const void* p) {
    uint32_t a;
    asm("{ .reg .u64 t; cvta.to.shared.u64 t, %1; cvt.u32.u64 %0, t; }" : "=r"(a) : "l"(p));
    return a;
}
__device__ __forceinline__ void cpa16(uint32_t s, const void* g) {
    asm volatile("cp.async.cg.shared.global [%0], [%1], 16;" :: "r"(s), "l"(g) : "memory");
}
__device__ __forceinline__ void ldsm4(uint32_t* r, uint32_t addr) {
    asm volatile("ldmatrix.sync.aligned.m8n8.x4.shared.b16 {%0,%1,%2,%3}, [%4];"
        : "=r"(r[0]), "=r"(r[1]), "=r"(r[2]), "=r"(r[3]) : "r"(addr));
}
__device__ __forceinline__ void mma16816(float* d, const uint32_t* a,
                                         uint32_t b0, uint32_t b1) {
    asm volatile(
        "mma.sync.aligned.m16n8k16.row.col.f32.bf16.bf16.f32 "
        "{%0,%1,%2,%3}, {%4,%5,%6,%7}, {%8,%9}, {%0,%1,%2,%3};"
        : "+f"(d[0]), "+f"(d[1]), "+f"(d[2]), "+f"(d[3])
        : "r"(a[0]), "r"(a[1]), "r"(a[2]), "r"(a[3]), "r"(b0), "r"(b1));
}
__device__ __forceinline__ uint32_t swz(uint32_t o) { return o ^ ((o >> 3) & 0x70); }

// ---------------------------------------------------------------------------
// K_init
// ---------------------------------------------------------------------------
__global__ void k_init(float* __restrict__ out) {
    int i = blockIdx.x * blockDim.x + threadIdx.x;
    if (i < BATCH * SEQ) g_scores[i] = 0.0f;
    if (i < BATCH * D2)  out[i] = 0.0f;
}

// ---------------------------------------------------------------------------
// K_precompute: c[b,h] = hidden[b,:] . W_attn[0:D2, h] + b_attn[h]
// ---------------------------------------------------------------------------
__global__ void k_precompute(const float* __restrict__ hidden,
                             const float* __restrict__ W,
                             const float* __restrict__ bias) {
    __shared__ float sh[D2];
    int b = blockIdx.x;
    for (int i = threadIdx.x; i < D2; i += blockDim.x) sh[i] = hidden[(size_t)b * D2 + i];
    __syncthreads();
    int h = threadIdx.x;
    float acc = bias[h];
#pragma unroll 8
    for (int k = 0; k < D2; ++k) acc = fmaf(sh[k], W[(size_t)k * H + h], acc);
    g_c[b * H + h] = acc;
}

// ---------------------------------------------------------------------------
// K_convB: W_e[k][n] -> g_Bh/g_Bl[n][k]  (bf16 hi/lo, transposed to n-major)
// ---------------------------------------------------------------------------
__global__ void k_convB(const float* __restrict__ W) {
    int idx = blockIdx.x * blockDim.x + threadIdx.x;   // H*D2
    int n = idx >> 10, k = idx & 1023;
    float x = W[(size_t)(D2 + k) * H + n];
    __nv_bfloat16 hi = __float2bfloat16(x);
    g_Bh[idx] = hi;
    g_Bl[idx] = __float2bfloat16(x - __bfloat162float(hi));
}

// ---------------------------------------------------------------------------
// K_convA: enc fp32 -> g_Ah/g_Al bf16 hi/lo (row-major unchanged)
// ---------------------------------------------------------------------------
__global__ void k_convA(const float4* __restrict__ enc4) {
    size_t i = (size_t)blockIdx.x * blockDim.x + threadIdx.x;   // MDIM*D2/4
    float4 v = enc4[i];
    __nv_bfloat16 h0 = __float2bfloat16(v.x), h1 = __float2bfloat16(v.y);
    __nv_bfloat16 h2 = __float2bfloat16(v.z), h3 = __float2bfloat16(v.w);
    __nv_bfloat162* ah = (__nv_bfloat162*)g_Ah;
    __nv_bfloat162* al = (__nv_bfloat162*)g_Al;
    ah[2*i]   = __halves2bfloat162(h0, h1);
    ah[2*i+1] = __halves2bfloat162(h2, h3);
    al[2*i]   = __halves2bfloat162(__float2bfloat16(v.x - __bfloat162float(h0)),
                                   __float2bfloat16(v.y - __bfloat162float(h1)));
    al[2*i+1] = __halves2bfloat162(__float2bfloat16(v.z - __bfloat162float(h2)),
                                   __float2bfloat16(v.w - __bfloat162float(h3)));
}

// ---------------------------------------------------------------------------
// K_scores: mma.sync bf16 3-term GEMM + tanh + dot(w_v) epilogue.
// Grid (2, 512): x = N tile (256 cols), y = M tile (128 rows). 256 threads.
// Warp tile 64x64 (warps 2m x 4n).
// ---------------------------------------------------------------------------
__device__ __forceinline__ void load_tile(uint32_t stage, int kt, int m0, int n0, int tid) {
    const size_t kOff = (size_t)kt * KT;
#pragma unroll
    for (int i = 0; i < 4; ++i) {          // A: 128 rows x 8 16B-chunks = 1024
        int c = tid + 256 * i;
        int row = c >> 3, c16 = c & 7;
        uint32_t so = swz((uint32_t)(row * 128 + c16 * 16));
        size_t e = (size_t)(m0 + row) * D2 + kOff + c16 * 8;
        cpa16(stage + AH_OFF + so, g_Ah + e);
        cpa16(stage + AL_OFF + so, g_Al + e);
    }
#pragma unroll
    for (int i = 0; i < 8; ++i) {          // B: 256 rows x 8 chunks = 2048
        int c = tid + 256 * i;
        int row = c >> 3, c16 = c & 7;
        uint32_t so = swz((uint32_t)(row * 128 + c16 * 16));
        size_t e = (size_t)(n0 + row) * D2 + kOff + c16 * 8;
        cpa16(stage + BH_OFF + so, g_Bh + e);
        cpa16(stage + BL_OFF + so, g_Bl + e);
    }
}

__global__ void __launch_bounds__(256, 1)
k_scores(const float* __restrict__ wv) {
    extern __shared__ char smem[];
    uint32_t sb = smem_u32(smem);
    sb = (sb + 127u) & ~127u;

    const int tid = threadIdx.x;
    const int wid = tid >> 5, lane = tid & 31;
    const int warp_m = wid & 1;           // 0..1 -> M offset *64
    const int warp_n = wid >> 1;          // 0..3 -> N offset *64
    const int g = lane >> 2, t = lane & 3;

    const int n0 = blockIdx.x * TILE_N;
    const int m0 = blockIdx.y * TILE_M;

    __shared__ float s_score[TILE_M];
    if (tid < TILE_M) s_score[tid] = 0.0f;

    // ldmatrix lane addressing constants
    const int a_lm = ((lane >> 3) & 1) * 8 + (lane & 7);   // m within 16
    const int a_kb = (lane >> 4) * 16;                     // k-byte within 32
    const int b_ln = (lane >> 4) * 8 + (lane & 7);         // n within 16
    const int b_kb = ((lane >> 3) & 1) * 16;

    float d[4][8][4];                     // [mt][nt][frag]  128 accum regs
#pragma unroll
    for (int mt = 0; mt < 4; mt++)
#pragma unroll
        for (int nt = 0; nt < 8; nt++)
#pragma unroll
            for (int e = 0; e < 4; e++) d[mt][nt][e] = 0.0f;

    // prologue: tile 0 -> stage 0
    load_tile(sb, 0, m0, n0, tid);
    asm volatile("cp.async.commit_group;" ::: "memory");

    for (int kt = 0; kt < NKT; ++kt) {
        const uint32_t cur = sb + (uint32_t)(kt & 1) * STAGE_BYTES;
        __syncthreads();   // everyone done computing the stage about to be overwritten
        if (kt + 1 < NKT) {
            load_tile(sb + (uint32_t)((kt + 1) & 1) * STAGE_BYTES, kt + 1, m0, n0, tid);
            asm volatile("cp.async.commit_group;" ::: "memory");
            asm volatile("cp.async.wait_group 1;" ::: "memory");
        } else {
            asm volatile("cp.async.wait_group 0;" ::: "memory");
        }
        __syncthreads();

#pragma unroll
        for (int ks = 0; ks < 4; ++ks) {
            uint32_t ah[4][4], bh[4][4], bl[4][4];
            uint32_t a_off[4];
#pragma unroll
            for (int mt = 0; mt < 4; mt++) {
                a_off[mt] = swz((uint32_t)((warp_m * 64 + mt * 16 + a_lm) * 128
                                           + ks * 32 + a_kb));
                ldsm4(ah[mt], cur + AH_OFF + a_off[mt]);
            }
#pragma unroll
            for (int p = 0; p < 4; p++) {
                uint32_t off = swz((uint32_t)((warp_n * 64 + p * 16 + b_ln) * 128
                                              + ks * 32 + b_kb));
                ldsm4(bh[p], cur + BH_OFF + off);
                ldsm4(bl[p], cur + BL_OFF + off);
            }
            // pass 1: Ah * Bh
#pragma unroll
            for (int mt = 0; mt < 4; mt++)
#pragma unroll
                for (int nt = 0; nt < 8; nt++)
                    mma16816(d[mt][nt], ah[mt], bh[nt >> 1][(nt & 1) * 2], bh[nt >> 1][(nt & 1) * 2 + 1]);
            // pass 2: Ah * Bl
#pragma unroll
            for (int mt = 0; mt < 4; mt++)
#pragma unroll
                for (int nt = 0; nt < 8; nt++)
                    mma16816(d[mt][nt], ah[mt], bl[nt >> 1][(nt & 1) * 2], bl[nt >> 1][(nt & 1) * 2 + 1]);
            // reload lo-A into the same registers, pass 3: Al * Bh
#pragma unroll
            for (int mt = 0; mt < 4; mt++)
                ldsm4(ah[mt], cur + AL_OFF + a_off[mt]);
#pragma unroll
            for (int mt = 0; mt < 4; mt++)
#pragma unroll
                for (int nt = 0; nt < 8; nt++)
                    mma16816(d[mt][nt], ah[mt], bh[nt >> 1][(nt & 1) * 2], bh[nt >> 1][(nt & 1) * 2 + 1]);
        }
    }

    // epilogue: tanh + dot(w_v), reduce to per-row scores
    const int b = m0 >> 12;
    float cv[16], wvv[16];
#pragma unroll
    for (int nt = 0; nt < 8; nt++)
#pragma unroll
        for (int e = 0; e < 2; e++) {
            int n = n0 + warp_n * 64 + nt * 8 + t * 2 + e;
            cv[nt * 2 + e]  = g_c[b * H + n];
            wvv[nt * 2 + e] = wv[n];
        }

#pragma unroll
    for (int mt = 0; mt < 4; mt++) {
        float r0 = 0.0f, r1 = 0.0f;      // rows g and g+8 of this m-tile
#pragma unroll
        for (int nt = 0; nt < 8; nt++) {
            r0 = fmaf(tanhf(d[mt][nt][0] + cv[nt * 2]),     wvv[nt * 2],     r0);
            r0 = fmaf(tanhf(d[mt][nt][1] + cv[nt * 2 + 1]), wvv[nt * 2 + 1], r0);
            r1 = fmaf(tanhf(d[mt][nt][2] + cv[nt * 2]),     wvv[nt * 2],     r1);
            r1 = fmaf(tanhf(d[mt][nt][3] + cv[nt * 2 + 1]), wvv[nt * 2 + 1], r1);
        }
        r0 += __shfl_xor_sync(0xffffffffu, r0, 1);
        r0 += __shfl_xor_sync(0xffffffffu, r0, 2);
        r1 += __shfl_xor_sync(0xffffffffu, r1, 1);
        r1 += __shfl_xor_sync(0xffffffffu, r1, 2);
        if (t == 0) {
            atomicAdd(&s_score[warp_m * 64 + mt * 16 + g],     r0);
            atomicAdd(&s_score[warp_m * 64 + mt * 16 + 8 + g], r1);
        }
    }
    __syncthreads();
    if (tid < TILE_M) atomicAdd(&g_scores[m0 + tid], s_score[tid]);
}

// ---------------------------------------------------------------------------
// K_softmax: per-batch softmax over S, in place.
// ---------------------------------------------------------------------------
__global__ void k_softmax() {
    int b = blockIdx.x, tid = threadIdx.x;
    float* sc = g_scores + (size_t)b * SEQ;
    __shared__ float sh[8];
    __shared__ float bc;

    float mx = -3.4e38f;
    for (int i = tid; i < SEQ; i += 256) mx = fmaxf(mx, sc[i]);
#pragma unroll
    for (int o = 16; o > 0; o >>= 1) mx = fmaxf(mx, __shfl_xor_sync(0xffffffffu, mx, o));
    if ((tid & 31) == 0) sh[tid >> 5] = mx;
    __syncthreads();
    if (tid == 0) {
        float m = sh[0];
        for (int i = 1; i < 8; i++) m = fmaxf(m, sh[i]);
        bc = m;
    }
    __syncthreads();
    mx = bc;

    float sum = 0.0f;
    for (int i = tid; i < SEQ; i += 256) {
        float e = expf(sc[i] - mx);
        sc[i] = e;
        sum += e;
    }
#pragma unroll
    for (int o = 16; o > 0; o >>= 1) sum += __shfl_xor_sync(0xffffffffu, sum, o);
    if ((tid & 31) == 0) sh[tid >> 5] = sum;
    __syncthreads();
    if (tid == 0) {
        float s = 0.0f;
        for (int i = 0; i < 8; i++) s += sh[i];
        bc = 1.0f / s;
    }
    __syncthreads();
    float inv = bc;
    for (int i = tid; i < SEQ; i += 256) sc[i] *= inv;
}

// ---------------------------------------------------------------------------
// K_context: context[b,d] = sum_s attn[b,s] * enc[b,s,d]
// ---------------------------------------------------------------------------
__global__ void k_context(const float* __restrict__ enc, float* __restrict__ out) {
    int b = blockIdx.y;
    int s0 = blockIdx.x * 256;
    int col = threadIdx.x * 4;

    const float* attn = g_scores + (size_t)b * SEQ + s0;
    const float* base = enc + ((size_t)b * SEQ + s0) * D2 + col;

    float4 acc = make_float4(0.f, 0.f, 0.f, 0.f);
#pragma unroll 4
    for (int s = 0; s < 256; s++) {
        float a = attn[s];
        float4 e = *(const float4*)(base + (size_t)s * D2);
        acc.x = fmaf(a, e.x, acc.x);
        acc.y = fmaf(a, e.y, acc.y);
        acc.z = fmaf(a, e.z, acc.z);
        acc.w = fmaf(a, e.w, acc.w);
    }
    float* o = out + (size_t)b * D2 + col;
    atomicAdd(&o[0], acc.x);
    atomicAdd(&o[1], acc.y);
    atomicAdd(&o[2], acc.z);
    atomicAdd(&o[3], acc.w);
}

// ---------------------------------------------------------------------------
extern "C" void kernel_launch(void* const* d_in, const int* in_sizes, int n_in,
                              void* d_out, int out_size) {
    const float* hidden = (const float*)d_in[0];  // [16, 1024]
    const float* enc    = (const float*)d_in[1];  // [16, 4096, 1024]
    const float* W      = (const float*)d_in[2];  // [2048, 512]
    const float* bias   = (const float*)d_in[3];  // [512]
    const float* wv     = (const float*)d_in[4];  // [512]
    float* out = (float*)d_out;                   // [16, 1024]

    static bool attr_set = false;
    if (!attr_set) {
        cudaFuncSetAttribute(k_scores, cudaFuncAttributeMaxDynamicSharedMemorySize, SMEM_ALLOC);
        attr_set = true;
    }

    k_init<<<256, 256>>>(out);
    k_precompute<<<BATCH, H>>>(hidden, W, bias);
    k_convB<<<(H * D2) / 256, 256>>>(W);
    k_convA<<<(int)(((size_t)MDIM * D2 / 4) / 256), 256>>>((const float4*)enc);

    dim3 gs(H / TILE_N, MDIM / TILE_M);   // (2, 512)
    k_scores<<<gs, 256, SMEM_ALLOC>>>(wv);

    k_softmax<<<BATCH, 256>>>();

    dim3 gc(SEQ / 256, BATCH);
    k_context<<<gc, 256>>>(enc, out);
}